// round 11
// baseline (speedup 1.0000x reference)
#include <cuda_runtime.h>
#include <math.h>

#define LL 4
#define BB 8
#define NS 1200
#define NL 128
#define CC 768
#define HH 448
#define WW 448
#define GS 56            // 448/8
#define GL 16            // 448/28
#define NWARP_S (LL*BB*NS)   // 38400 (divisible by 8)
#define NWARP_L (LL*BB*NL)   // 4096  (divisible by 8)
#define CHUNK_S 240          // 1200 = 5 * 240
#define NCHUNK_S 5
#define NBLK_STATS (LL*BB*NCHUNK_S + LL*BB)   // 160 + 32 = 192

// Scratch (no allocation allowed)
__device__ float         g_d_s[NWARP_S];
__device__ float         g_d_l[NWARP_L];
__device__ unsigned char g_nzT_s[LL*NS*BB];   // [l][n][b] -> 8B aligned per (l,n)
__device__ unsigned char g_nzT_l[LL*NL*BB];
__device__ float g_sp[NBLK_STATS], g_sn[NBLK_STATS];
__device__ int   g_cp[NBLK_STATS], g_cn[NBLK_STATS];

// ---------------------------------------------------------------------------
// Kernel 1: per-row distance + nonzero flag (R8 configuration — best measured:
// 48 regs, 5 CTAs/SM, 5.71 TB/s). One warp per row; block's 8 rows share lb,
// kernel vector staged in SMEM once per block.
__global__ void __launch_bounds__(256) dist_fused(const float* __restrict__ sel_s,
                                                  const float* __restrict__ ker_s,
                                                  const float* __restrict__ sel_l,
                                                  const float* __restrict__ ker_l) {
    __shared__ float4 s_ker[CC/4];   // 3 KB

    int w    = blockIdx.x * 8 + (threadIdx.x >> 5);
    int lane = threadIdx.x & 31;

    const float* sel; const float* ker;
    float* dOut; unsigned char* nzT;
    int N, row;
    bool live = true;
    if (w < NWARP_S) {
        row = w; N = NS; sel = sel_s; ker = ker_s; dOut = g_d_s; nzT = g_nzT_s;
    } else {
        row = w - NWARP_S;
        if (row >= NWARP_L) { live = false; row = 0; }
        N = NL; sel = sel_l; ker = ker_l; dOut = g_d_l; nzT = g_nzT_l;
    }
    int lb = row / N, n = row % N;
    int l = lb / BB, b = lb % BB;

    // Cooperative ker stage: 192 float4 loads by threads 0..191 (same lb for
    // the whole block). Issued before the streaming loads.
    if (threadIdx.x < CC/4) {
        const float4* kg = reinterpret_cast<const float4*>(ker) + (size_t)lb * (CC/4);
        s_ker[threadIdx.x] = __ldg(&kg[threadIdx.x]);
    }

    const float4* s4 = reinterpret_cast<const float4*>(sel) + (size_t)row * (CC/4);

    float4 sv[6];
    #pragma unroll
    for (int i = 0; i < 6; i++) sv[i] = __ldcs(&s4[lane + 32*i]);   // streaming DRAM

    __syncthreads();

    float acc = 0.f;
    unsigned orb = 0u;
    #pragma unroll
    for (int i = 0; i < 6; i++) {
        float4 kv = s_ker[lane + 32*i];                              // LDS.128, conflict-free
        float d0 = kv.x - sv[i].x, d1 = kv.y - sv[i].y;
        float d2 = kv.z - sv[i].z, d3 = kv.w - sv[i].w;
        acc = fmaf(d0, d0, acc); acc = fmaf(d1, d1, acc);
        acc = fmaf(d2, d2, acc); acc = fmaf(d3, d3, acc);
        orb |= __float_as_uint(sv[i].x) | __float_as_uint(sv[i].y)
             | __float_as_uint(sv[i].z) | __float_as_uint(sv[i].w);
    }
    #pragma unroll
    for (int o = 16; o; o >>= 1) {
        acc += __shfl_xor_sync(0xffffffffu, acc, o);
        orb |= __shfl_xor_sync(0xffffffffu, orb, o);
    }
    if (live && lane == 0) {
        dOut[row] = sqrtf(acc);
        nzT[(size_t)(l*N + n)*BB + b] = ((orb & 0x7fffffffu) != 0u) ? 1 : 0;
    }
}

// ---------------------------------------------------------------------------
// Kernel 2: partial masked sums (known good).
__global__ void __launch_bounds__(256) stats_partial(const int* __restrict__ idx_s,
                                                     const int* __restrict__ idx_l,
                                                     const float* __restrict__ fk) {
    int blk = blockIdx.x;
    bool is_s = blk < LL*BB*NCHUNK_S;
    int g, n0, nCnt;
    if (is_s) { g = blk / NCHUNK_S; n0 = (blk % NCHUNK_S) * CHUNK_S; nCnt = CHUNK_S; }
    else      { g = blk - LL*BB*NCHUNK_S; n0 = 0; nCnt = NL; }
    int l = g / BB, b = g % BB;

    float sp = 0.f, sn = 0.f;
    int cp = 0, cn = 0;
    int t = (int)threadIdx.x;
    if (t < nCnt) {
        int n = n0 + t;
        unsigned long long nz64;
        float d; int idx; bool member;
        if (is_s) {
            nz64 = *reinterpret_cast<const unsigned long long*>(g_nzT_s + (size_t)(l*NS + n)*8);
            d    = g_d_s[g*NS + n];
            idx  = idx_s[g*NS + n];
            int gy = idx / GS, gx = idx % GS;
            member = fk[(size_t)b*HH*WW + (size_t)gy*8*WW + gx*8] > 0.f;
        } else {
            nz64 = *reinterpret_cast<const unsigned long long*>(g_nzT_l + (size_t)(l*NL + n)*8);
            d    = g_d_l[g*NL + n];
            idx  = idx_l[g*NL + n];
            int gy = idx / GL, gx = idx % GL;
            member = fk[(size_t)b*HH*WW + (size_t)gy*28*WW + gx*28] > 0.f;
        }
        if (nz64 != 0ull) {
            if (member) { sp = d; cp = 1; } else { sn = d; cn = 1; }
        }
    }
    #pragma unroll
    for (int o = 16; o; o >>= 1) {
        sp += __shfl_xor_sync(0xffffffffu, sp, o);
        sn += __shfl_xor_sync(0xffffffffu, sn, o);
        cp += __shfl_xor_sync(0xffffffffu, cp, o);
        cn += __shfl_xor_sync(0xffffffffu, cn, o);
    }
    __shared__ float s_sp[8], s_sn[8];
    __shared__ int   s_cp[8], s_cn[8];
    int wid = t >> 5, ln = t & 31;
    if (ln == 0) { s_sp[wid] = sp; s_sn[wid] = sn; s_cp[wid] = cp; s_cn[wid] = cn; }
    __syncthreads();
    if (t == 0) {
        float tsp = 0.f, tsn = 0.f; int tcp = 0, tcn = 0;
        #pragma unroll
        for (int wI = 0; wI < 8; wI++) { tsp += s_sp[wI]; tsn += s_sn[wI]; tcp += s_cp[wI]; tcn += s_cn[wI]; }
        g_sp[blk] = tsp; g_sn[blk] = tsn; g_cp[blk] = tcp; g_cn[blk] = tcn;
    }
}

// ---------------------------------------------------------------------------
// Kernel 3: finish. PDL secondary of stats_partial: launches concurrently
// (1 block / 64 threads — negligible SM footprint), waits for stats' writes.
__global__ void final_kernel(float* __restrict__ out) {
    cudaGridDependencySynchronize();

    int t = (int)threadIdx.x;   // 0..63
    float sp = 0.f, sn = 0.f; int cp = 0, cn = 0;
    if (t < 32) {
        #pragma unroll
        for (int c = 0; c < NCHUNK_S; c++) {
            int s = t*NCHUNK_S + c;
            sp += g_sp[s]; sn += g_sn[s]; cp += g_cp[s]; cn += g_cn[s];
        }
    } else {
        int s = LL*BB*NCHUNK_S + (t - 32);
        sp = g_sp[s]; sn = g_sn[s]; cp = g_cp[s]; cn = g_cn[s];
    }
    float ap = sp / (float)max(cp, 1);
    float an = sn / (float)max(cn, 1);
    float x = ap - an;
    float loss = fmaxf(x, 0.f) + log1pf(expf(-fabsf(x)));   // stable softplus
    int act = (cp > 0 && cn > 0) ? 1 : 0;

    __shared__ float s_loss[64];
    __shared__ int   s_act[64];
    s_loss[t] = loss; s_act[t] = act;
    __syncthreads();
    if (t < 32) {
        int   as  = s_act[t];
        int   al  = s_act[32 + t] & as;        // act_l &= act_s
        float tot = (as ? s_loss[t] : 0.f) + (al ? s_loss[32 + t] : 0.f);
        int times = as + al;
        #pragma unroll
        for (int o = 16; o; o >>= 1) {
            tot   += __shfl_xor_sync(0xffffffffu, tot, o);
            times += __shfl_xor_sync(0xffffffffu, times, o);
        }
        if (t == 0) out[0] = (times > 0) ? tot / (float)times : 0.f;
    }
}

// ---------------------------------------------------------------------------
extern "C" void kernel_launch(void* const* d_in, const int* in_sizes, int n_in,
                              void* d_out, int out_size) {
    const float* sel_s = (const float*)d_in[0];
    const int*   idx_s = (const int*)  d_in[1];
    const float* sel_l = (const float*)d_in[2];
    const int*   idx_l = (const int*)  d_in[3];
    const float* ker_s = (const float*)d_in[4];
    const float* ker_l = (const float*)d_in[5];
    const float* fk    = (const float*)d_in[6];

    int nblk = (NWARP_S + NWARP_L) / 8;   // 5312, never straddles lb
    dist_fused<<<nblk, 256>>>(sel_s, ker_s, sel_l, ker_l);
    stats_partial<<<NBLK_STATS, 256>>>(idx_s, idx_l, fk);

    // final_kernel as PDL secondary: overlaps its launch with stats_partial.
    cudaLaunchAttribute attr[1];
    attr[0].id = cudaLaunchAttributeProgrammaticStreamSerialization;
    attr[0].val.programmaticStreamSerializationAllowed = 1;
    cudaLaunchConfig_t cfg = {};
    cfg.gridDim  = dim3(1, 1, 1);
    cfg.blockDim = dim3(64, 1, 1);
    cfg.dynamicSmemBytes = 0;
    cfg.stream = 0;
    cfg.attrs = attr;
    cfg.numAttrs = 1;
    cudaLaunchKernelEx(&cfg, final_kernel, (float*)d_out);
}

// round 12
// speedup vs baseline: 1.0327x; 1.0327x over previous
#include <cuda_runtime.h>
#include <math.h>

#define LL 4
#define BB 8
#define NS 1200
#define NL 128
#define CC 768
#define HH 448
#define WW 448
#define GS 56            // 448/8
#define GL 16            // 448/28
#define NROW_S (LL*BB*NS)    // 38400 (divisible by 16)
#define NROW_L (LL*BB*NL)    // 4096  (divisible by 16)
#define NBLK_DIST ((NROW_S + NROW_L) / 16)   // 2656, 16 rows per block, one lb
#define CHUNK_S 240          // 1200 = 5 * 240
#define NCHUNK_S 5
#define NBLK_STATS (LL*BB*NCHUNK_S + LL*BB)   // 160 + 32 = 192

// Scratch (no allocation allowed)
__device__ float         g_d_s[NROW_S];
__device__ float         g_d_l[NROW_L];
__device__ unsigned char g_nzT_s[LL*NS*BB];   // [l][n][b] -> 8B aligned per (l,n)
__device__ unsigned char g_nzT_l[LL*NL*BB];
__device__ float g_sp[NBLK_STATS], g_sn[NBLK_STATS];
__device__ int   g_cp[NBLK_STATS], g_cn[NBLK_STATS];

// ---------------------------------------------------------------------------
// Kernel 1: distance + nonzero flag. 2 consecutive rows per warp, 16 rows per
// block (one lb), kernel vector staged in SMEM once per block. Per warp:
// 12 independent streaming LDG.128, zero ker LDGs -> max bytes in flight.
__global__ void __launch_bounds__(256) dist_fused(const float* __restrict__ sel_s,
                                                  const float* __restrict__ ker_s,
                                                  const float* __restrict__ sel_l,
                                                  const float* __restrict__ ker_l) {
    __shared__ float4 s_ker[CC/4];   // 3 KB

    int wid  = threadIdx.x >> 5;
    int lane = threadIdx.x & 31;
    int base = blockIdx.x * 16;      // first row of this block

    const float* sel; const float* ker;
    float* dOut; unsigned char* nzT;
    int N, r0;
    if (base < NROW_S) {
        r0 = base + wid*2; N = NS; sel = sel_s; ker = ker_s; dOut = g_d_s; nzT = g_nzT_s;
    } else {
        r0 = base - NROW_S + wid*2; N = NL; sel = sel_l; ker = ker_l; dOut = g_d_l; nzT = g_nzT_l;
    }
    int lb = r0 / N, n0 = r0 % N;    // whole block shares lb (N % 16 == 0)
    int l = lb / BB, b = lb % BB;

    // Cooperative ker stage (same lb for whole block), issued first.
    if (threadIdx.x < CC/4) {
        const float4* kg = reinterpret_cast<const float4*>(ker) + (size_t)lb * (CC/4);
        s_ker[threadIdx.x] = __ldg(&kg[threadIdx.x]);
    }

    const float4* s4 = reinterpret_cast<const float4*>(sel) + (size_t)r0 * (CC/4);

    float4 sv0[6], sv1[6];
    #pragma unroll
    for (int i = 0; i < 6; i++) sv0[i] = __ldcs(&s4[lane + 32*i]);            // row r0
    #pragma unroll
    for (int i = 0; i < 6; i++) sv1[i] = __ldcs(&s4[(CC/4) + lane + 32*i]);   // row r0+1

    __syncthreads();

    float a0 = 0.f, a1 = 0.f;
    unsigned o0 = 0u, o1 = 0u;
    #pragma unroll
    for (int i = 0; i < 6; i++) {
        float4 kv = s_ker[lane + 32*i];                                       // LDS.128
        float d0 = kv.x - sv0[i].x, d1 = kv.y - sv0[i].y;
        float d2 = kv.z - sv0[i].z, d3 = kv.w - sv0[i].w;
        a0 = fmaf(d0, d0, a0); a0 = fmaf(d1, d1, a0);
        a0 = fmaf(d2, d2, a0); a0 = fmaf(d3, d3, a0);
        o0 |= __float_as_uint(sv0[i].x) | __float_as_uint(sv0[i].y)
            | __float_as_uint(sv0[i].z) | __float_as_uint(sv0[i].w);
        float e0 = kv.x - sv1[i].x, e1 = kv.y - sv1[i].y;
        float e2 = kv.z - sv1[i].z, e3 = kv.w - sv1[i].w;
        a1 = fmaf(e0, e0, a1); a1 = fmaf(e1, e1, a1);
        a1 = fmaf(e2, e2, a1); a1 = fmaf(e3, e3, a1);
        o1 |= __float_as_uint(sv1[i].x) | __float_as_uint(sv1[i].y)
            | __float_as_uint(sv1[i].z) | __float_as_uint(sv1[i].w);
    }
    #pragma unroll
    for (int o = 16; o; o >>= 1) {
        a0 += __shfl_xor_sync(0xffffffffu, a0, o);
        a1 += __shfl_xor_sync(0xffffffffu, a1, o);
        o0 |= __shfl_xor_sync(0xffffffffu, o0, o);
        o1 |= __shfl_xor_sync(0xffffffffu, o1, o);
    }
    if (lane == 0) {
        dOut[r0]     = sqrtf(a0);
        dOut[r0 + 1] = sqrtf(a1);
        nzT[(size_t)(l*N + n0    )*BB + b] = ((o0 & 0x7fffffffu) != 0u) ? 1 : 0;
        nzT[(size_t)(l*N + n0 + 1)*BB + b] = ((o1 & 0x7fffffffu) != 0u) ? 1 : 0;
    }
}

// ---------------------------------------------------------------------------
// Kernel 2: partial masked sums (known good).
__global__ void __launch_bounds__(256) stats_partial(const int* __restrict__ idx_s,
                                                     const int* __restrict__ idx_l,
                                                     const float* __restrict__ fk) {
    int blk = blockIdx.x;
    bool is_s = blk < LL*BB*NCHUNK_S;
    int g, n0, nCnt;
    if (is_s) { g = blk / NCHUNK_S; n0 = (blk % NCHUNK_S) * CHUNK_S; nCnt = CHUNK_S; }
    else      { g = blk - LL*BB*NCHUNK_S; n0 = 0; nCnt = NL; }
    int l = g / BB, b = g % BB;

    float sp = 0.f, sn = 0.f;
    int cp = 0, cn = 0;
    int t = (int)threadIdx.x;
    if (t < nCnt) {
        int n = n0 + t;
        unsigned long long nz64;
        float d; int idx; bool member;
        if (is_s) {
            nz64 = *reinterpret_cast<const unsigned long long*>(g_nzT_s + (size_t)(l*NS + n)*8);
            d    = g_d_s[g*NS + n];
            idx  = idx_s[g*NS + n];
            int gy = idx / GS, gx = idx % GS;
            member = fk[(size_t)b*HH*WW + (size_t)gy*8*WW + gx*8] > 0.f;
        } else {
            nz64 = *reinterpret_cast<const unsigned long long*>(g_nzT_l + (size_t)(l*NL + n)*8);
            d    = g_d_l[g*NL + n];
            idx  = idx_l[g*NL + n];
            int gy = idx / GL, gx = idx % GL;
            member = fk[(size_t)b*HH*WW + (size_t)gy*28*WW + gx*28] > 0.f;
        }
        if (nz64 != 0ull) {
            if (member) { sp = d; cp = 1; } else { sn = d; cn = 1; }
        }
    }
    #pragma unroll
    for (int o = 16; o; o >>= 1) {
        sp += __shfl_xor_sync(0xffffffffu, sp, o);
        sn += __shfl_xor_sync(0xffffffffu, sn, o);
        cp += __shfl_xor_sync(0xffffffffu, cp, o);
        cn += __shfl_xor_sync(0xffffffffu, cn, o);
    }
    __shared__ float s_sp[8], s_sn[8];
    __shared__ int   s_cp[8], s_cn[8];
    int wid = t >> 5, ln = t & 31;
    if (ln == 0) { s_sp[wid] = sp; s_sn[wid] = sn; s_cp[wid] = cp; s_cn[wid] = cn; }
    __syncthreads();
    if (t == 0) {
        float tsp = 0.f, tsn = 0.f; int tcp = 0, tcn = 0;
        #pragma unroll
        for (int wI = 0; wI < 8; wI++) { tsp += s_sp[wI]; tsn += s_sn[wI]; tcp += s_cp[wI]; tcn += s_cn[wI]; }
        g_sp[blk] = tsp; g_sn[blk] = tsn; g_cp[blk] = tcp; g_cn[blk] = tcn;
    }
}

// ---------------------------------------------------------------------------
// Kernel 3: finish.
__global__ void final_kernel(float* __restrict__ out) {
    int t = (int)threadIdx.x;   // 0..63
    float sp = 0.f, sn = 0.f; int cp = 0, cn = 0;
    if (t < 32) {
        #pragma unroll
        for (int c = 0; c < NCHUNK_S; c++) {
            int s = t*NCHUNK_S + c;
            sp += g_sp[s]; sn += g_sn[s]; cp += g_cp[s]; cn += g_cn[s];
        }
    } else {
        int s = LL*BB*NCHUNK_S + (t - 32);
        sp = g_sp[s]; sn = g_sn[s]; cp = g_cp[s]; cn = g_cn[s];
    }
    float ap = sp / (float)max(cp, 1);
    float an = sn / (float)max(cn, 1);
    float x = ap - an;
    float loss = fmaxf(x, 0.f) + log1pf(expf(-fabsf(x)));   // stable softplus
    int act = (cp > 0 && cn > 0) ? 1 : 0;

    __shared__ float s_loss[64];
    __shared__ int   s_act[64];
    s_loss[t] = loss; s_act[t] = act;
    __syncthreads();
    if (t < 32) {
        int   as  = s_act[t];
        int   al  = s_act[32 + t] & as;        // act_l &= act_s
        float tot = (as ? s_loss[t] : 0.f) + (al ? s_loss[32 + t] : 0.f);
        int times = as + al;
        #pragma unroll
        for (int o = 16; o; o >>= 1) {
            tot   += __shfl_xor_sync(0xffffffffu, tot, o);
            times += __shfl_xor_sync(0xffffffffu, times, o);
        }
        if (t == 0) out[0] = (times > 0) ? tot / (float)times : 0.f;
    }
}

// ---------------------------------------------------------------------------
extern "C" void kernel_launch(void* const* d_in, const int* in_sizes, int n_in,
                              void* d_out, int out_size) {
    const float* sel_s = (const float*)d_in[0];
    const int*   idx_s = (const int*)  d_in[1];
    const float* sel_l = (const float*)d_in[2];
    const int*   idx_l = (const int*)  d_in[3];
    const float* ker_s = (const float*)d_in[4];
    const float* ker_l = (const float*)d_in[5];
    const float* fk    = (const float*)d_in[6];

    dist_fused<<<NBLK_DIST, 256>>>(sel_s, ker_s, sel_l, ker_l);
    stats_partial<<<NBLK_STATS, 256>>>(idx_s, idx_l, fk);
    final_kernel<<<1, 64>>>((float*)d_out);
}

// round 13
// speedup vs baseline: 1.0339x; 1.0012x over previous
#include <cuda_runtime.h>
#include <math.h>

#define LL 4
#define BB 8
#define NS 1200
#define NL 128
#define CC 768
#define HH 448
#define WW 448
#define GS 56            // 448/8
#define GL 16            // 448/28
#define NROW_S (LL*BB*NS)    // 38400 (divisible by 16)
#define NROW_L (LL*BB*NL)    // 4096  (divisible by 16)
#define NBLK_DIST ((NROW_S + NROW_L) / 16)   // 2656, 16 rows per block, one lb
#define CHUNK_S 240          // 1200 = 5 * 240
#define NCHUNK_S 5
#define NBLK_STATS (LL*BB*NCHUNK_S + LL*BB)   // 160 + 32 = 192

// Scratch (no allocation allowed)
__device__ float         g_d_s[NROW_S];
__device__ float         g_d_l[NROW_L];
__device__ unsigned char g_nzT_s[LL*NS*BB];   // [l][n][b] -> 8B aligned per (l,n)
__device__ unsigned char g_nzT_l[LL*NL*BB];
__device__ float g_sp[NBLK_STATS], g_sn[NBLK_STATS];
__device__ int   g_cp[NBLK_STATS], g_cn[NBLK_STATS];
__device__ unsigned int g_counter = 0;

// ---------------------------------------------------------------------------
// Kernel 1: distance + nonzero flag (R12 configuration — best measured:
// 5.81 TB/s). 2 consecutive rows per warp, 16 rows per block (one lb),
// kernel vector staged in SMEM once per block.
__global__ void __launch_bounds__(256) dist_fused(const float* __restrict__ sel_s,
                                                  const float* __restrict__ ker_s,
                                                  const float* __restrict__ sel_l,
                                                  const float* __restrict__ ker_l) {
    __shared__ float4 s_ker[CC/4];   // 3 KB

    int wid  = threadIdx.x >> 5;
    int lane = threadIdx.x & 31;
    int base = blockIdx.x * 16;      // first row of this block

    const float* sel; const float* ker;
    float* dOut; unsigned char* nzT;
    int N, r0;
    if (base < NROW_S) {
        r0 = base + wid*2; N = NS; sel = sel_s; ker = ker_s; dOut = g_d_s; nzT = g_nzT_s;
    } else {
        r0 = base - NROW_S + wid*2; N = NL; sel = sel_l; ker = ker_l; dOut = g_d_l; nzT = g_nzT_l;
    }
    int lb = r0 / N, n0 = r0 % N;    // whole block shares lb (N % 16 == 0)
    int l = lb / BB, b = lb % BB;

    // Cooperative ker stage (same lb for whole block), issued first.
    if (threadIdx.x < CC/4) {
        const float4* kg = reinterpret_cast<const float4*>(ker) + (size_t)lb * (CC/4);
        s_ker[threadIdx.x] = __ldg(&kg[threadIdx.x]);
    }

    const float4* s4 = reinterpret_cast<const float4*>(sel) + (size_t)r0 * (CC/4);

    float4 sv0[6], sv1[6];
    #pragma unroll
    for (int i = 0; i < 6; i++) sv0[i] = __ldcs(&s4[lane + 32*i]);            // row r0
    #pragma unroll
    for (int i = 0; i < 6; i++) sv1[i] = __ldcs(&s4[(CC/4) + lane + 32*i]);   // row r0+1

    __syncthreads();

    float a0 = 0.f, a1 = 0.f;
    unsigned o0 = 0u, o1 = 0u;
    #pragma unroll
    for (int i = 0; i < 6; i++) {
        float4 kv = s_ker[lane + 32*i];                                       // LDS.128
        float d0 = kv.x - sv0[i].x, d1 = kv.y - sv0[i].y;
        float d2 = kv.z - sv0[i].z, d3 = kv.w - sv0[i].w;
        a0 = fmaf(d0, d0, a0); a0 = fmaf(d1, d1, a0);
        a0 = fmaf(d2, d2, a0); a0 = fmaf(d3, d3, a0);
        o0 |= __float_as_uint(sv0[i].x) | __float_as_uint(sv0[i].y)
            | __float_as_uint(sv0[i].z) | __float_as_uint(sv0[i].w);
        float e0 = kv.x - sv1[i].x, e1 = kv.y - sv1[i].y;
        float e2 = kv.z - sv1[i].z, e3 = kv.w - sv1[i].w;
        a1 = fmaf(e0, e0, a1); a1 = fmaf(e1, e1, a1);
        a1 = fmaf(e2, e2, a1); a1 = fmaf(e3, e3, a1);
        o1 |= __float_as_uint(sv1[i].x) | __float_as_uint(sv1[i].y)
            | __float_as_uint(sv1[i].z) | __float_as_uint(sv1[i].w);
    }
    #pragma unroll
    for (int o = 16; o; o >>= 1) {
        a0 += __shfl_xor_sync(0xffffffffu, a0, o);
        a1 += __shfl_xor_sync(0xffffffffu, a1, o);
        o0 |= __shfl_xor_sync(0xffffffffu, o0, o);
        o1 |= __shfl_xor_sync(0xffffffffu, o1, o);
    }
    if (lane == 0) {
        dOut[r0]     = sqrtf(a0);
        dOut[r0 + 1] = sqrtf(a1);
        nzT[(size_t)(l*N + n0    )*BB + b] = ((o0 & 0x7fffffffu) != 0u) ? 1 : 0;
        nzT[(size_t)(l*N + n0 + 1)*BB + b] = ((o1 & 0x7fffffffu) != 0u) ? 1 : 0;
    }
}

// ---------------------------------------------------------------------------
// Kernel 2: partial masked sums + fused final (last-block, PARALLEL slot read).
__global__ void __launch_bounds__(256) stats_final(const int* __restrict__ idx_s,
                                                   const int* __restrict__ idx_l,
                                                   const float* __restrict__ fk,
                                                   float* __restrict__ out) {
    int blk = blockIdx.x;
    bool is_s = blk < LL*BB*NCHUNK_S;
    int g, n0, nCnt;
    if (is_s) { g = blk / NCHUNK_S; n0 = (blk % NCHUNK_S) * CHUNK_S; nCnt = CHUNK_S; }
    else      { g = blk - LL*BB*NCHUNK_S; n0 = 0; nCnt = NL; }
    int l = g / BB, b = g % BB;

    float sp = 0.f, sn = 0.f;
    int cp = 0, cn = 0;
    int t = (int)threadIdx.x;
    if (t < nCnt) {
        int n = n0 + t;
        unsigned long long nz64;
        float d; int idx; bool member;
        if (is_s) {
            nz64 = *reinterpret_cast<const unsigned long long*>(g_nzT_s + (size_t)(l*NS + n)*8);
            d    = g_d_s[g*NS + n];
            idx  = idx_s[g*NS + n];
            int gy = idx / GS, gx = idx % GS;
            member = fk[(size_t)b*HH*WW + (size_t)gy*8*WW + gx*8] > 0.f;
        } else {
            nz64 = *reinterpret_cast<const unsigned long long*>(g_nzT_l + (size_t)(l*NL + n)*8);
            d    = g_d_l[g*NL + n];
            idx  = idx_l[g*NL + n];
            int gy = idx / GL, gx = idx % GL;
            member = fk[(size_t)b*HH*WW + (size_t)gy*28*WW + gx*28] > 0.f;
        }
        if (nz64 != 0ull) {
            if (member) { sp = d; cp = 1; } else { sn = d; cn = 1; }
        }
    }
    #pragma unroll
    for (int o = 16; o; o >>= 1) {
        sp += __shfl_xor_sync(0xffffffffu, sp, o);
        sn += __shfl_xor_sync(0xffffffffu, sn, o);
        cp += __shfl_xor_sync(0xffffffffu, cp, o);
        cn += __shfl_xor_sync(0xffffffffu, cn, o);
    }
    __shared__ float s_sp[8], s_sn[8];
    __shared__ int   s_cp[8], s_cn[8];
    int wid = t >> 5, ln = t & 31;
    if (ln == 0) { s_sp[wid] = sp; s_sn[wid] = sn; s_cp[wid] = cp; s_cn[wid] = cn; }
    __syncthreads();
    if (t == 0) {
        float tsp = 0.f, tsn = 0.f; int tcp = 0, tcn = 0;
        #pragma unroll
        for (int wI = 0; wI < 8; wI++) { tsp += s_sp[wI]; tsn += s_sn[wI]; tcp += s_cp[wI]; tcn += s_cn[wI]; }
        g_sp[blk] = tsp; g_sn[blk] = tsn; g_cp[blk] = tcp; g_cn[blk] = tcn;
    }

    // ---- last-block epilogue: parallel slot read, smem-only reduction ----
    __shared__ bool amLast;
    __threadfence();
    if (t == 0) {
        unsigned int v = atomicAdd(&g_counter, 1u);
        amLast = (v == (unsigned)(NBLK_STATS - 1));
    }
    __syncthreads();
    if (!amLast) return;
    if (t == 0) g_counter = 0;           // reset for next graph replay

    // 192 threads load all slots in parallel (independent -> one latency).
    __shared__ float sl_sp[NBLK_STATS], sl_sn[NBLK_STATS];
    __shared__ int   sl_cp[NBLK_STATS], sl_cn[NBLK_STATS];
    if (t < NBLK_STATS) {
        volatile float* vp = g_sp; volatile float* vn = g_sn;
        volatile int*   cpv = g_cp; volatile int* cnv = g_cn;
        sl_sp[t] = vp[t]; sl_sn[t] = vn[t];
        sl_cp[t] = cpv[t]; sl_cn[t] = cnv[t];
    }
    __syncthreads();

    __shared__ float s_loss[64];
    __shared__ int   s_act[64];
    if (t < 64) {
        float psp = 0.f, psn = 0.f; int pcp = 0, pcn = 0;
        if (t < 32) {
            #pragma unroll
            for (int c = 0; c < NCHUNK_S; c++) {
                int s = t*NCHUNK_S + c;
                psp += sl_sp[s]; psn += sl_sn[s]; pcp += sl_cp[s]; pcn += sl_cn[s];
            }
        } else {
            int s = LL*BB*NCHUNK_S + (t - 32);
            psp = sl_sp[s]; psn = sl_sn[s]; pcp = sl_cp[s]; pcn = sl_cn[s];
        }
        float ap = psp / (float)max(pcp, 1);
        float an = psn / (float)max(pcn, 1);
        float x = ap - an;
        s_loss[t] = fmaxf(x, 0.f) + log1pf(expf(-fabsf(x)));   // stable softplus
        s_act[t]  = (pcp > 0 && pcn > 0) ? 1 : 0;
    }
    __syncthreads();
    if (t < 32) {
        int   as  = s_act[t];
        int   al  = s_act[32 + t] & as;        // act_l &= act_s
        float tot = (as ? s_loss[t] : 0.f) + (al ? s_loss[32 + t] : 0.f);
        int times = as + al;
        #pragma unroll
        for (int o = 16; o; o >>= 1) {
            tot   += __shfl_xor_sync(0xffffffffu, tot, o);
            times += __shfl_xor_sync(0xffffffffu, times, o);
        }
        if (t == 0) out[0] = (times > 0) ? tot / (float)times : 0.f;
    }
}

// ---------------------------------------------------------------------------
extern "C" void kernel_launch(void* const* d_in, const int* in_sizes, int n_in,
                              void* d_out, int out_size) {
    const float* sel_s = (const float*)d_in[0];
    const int*   idx_s = (const int*)  d_in[1];
    const float* sel_l = (const float*)d_in[2];
    const int*   idx_l = (const int*)  d_in[3];
    const float* ker_s = (const float*)d_in[4];
    const float* ker_l = (const float*)d_in[5];
    const float* fk    = (const float*)d_in[6];

    dist_fused<<<NBLK_DIST, 256>>>(sel_s, ker_s, sel_l, ker_l);
    stats_final<<<NBLK_STATS, 256>>>(idx_s, idx_l, fk, (float*)d_out);
}